// round 16
// baseline (speedup 1.0000x reference)
#include <cuda_runtime.h>
#include <cstdint>

#define BATCH 2048
#define NH    512
#define HC    256
#define ROWS  16            // rows per chunk (one m16 tile)
#define IDXCAP 128
#define GRID  296
#define NTOPI (BATCH / ROWS)       // 128 top items
#define NQ    (HC + NTOPI)         // 384 items
#define NTHR  256
#define XPITCH 1040         // 512 bf16 + 16B pad -> conflict-free ldmatrix

// smem byte offsets
#define OFF_XH  0                   // 16 * 1040
#define OFF_XL  16640
#define OFF_LG  33280               // 16*256*4
#define OFF_IDX 49664
#define OFF_CNT (OFF_IDX + IDXCAP * 4)
#define OFF_POP (OFF_CNT + 4)
#define SMEM_BYTES (OFF_POP + 12)   // ~50.2 KB -> 2 CTAs/SM

__device__ float g_top_prob[BATCH];
__device__ float g_bot_prob[BATCH];
__device__ int   g_queue;
__device__ int   g_done;

// ---------------- PTX helpers (all baseline ISA, no 'a' features) ----------
__device__ __forceinline__ uint32_t cvt2bf(float hi, float lo) {
    uint32_t r; asm("cvt.rn.bf16x2.f32 %0, %1, %2;" : "=r"(r) : "f"(hi), "f"(lo));
    return r;
}
__device__ __forceinline__ void sts64(uint32_t a, uint64_t v) {
    asm volatile("st.shared.b64 [%0], %1;" :: "r"(a), "l"(v));
}
__device__ __forceinline__ void ldmx4(uint32_t* r, uint32_t addr) {
    asm volatile("ldmatrix.sync.aligned.m8n8.x4.shared.b16 {%0,%1,%2,%3}, [%4];"
        : "=r"(r[0]), "=r"(r[1]), "=r"(r[2]), "=r"(r[3]) : "r"(addr));
}
__device__ __forceinline__ void mma16816(float* d, const uint32_t* a,
                                         const uint32_t* b) {
    asm volatile(
        "mma.sync.aligned.m16n8k16.row.col.f32.bf16.bf16.f32 "
        "{%0,%1,%2,%3}, {%4,%5,%6,%7}, {%8,%9}, {%0,%1,%2,%3};"
        : "+f"(d[0]), "+f"(d[1]), "+f"(d[2]), "+f"(d[3])
        : "r"(a[0]), "r"(a[1]), "r"(a[2]), "r"(a[3]), "r"(b[0]), "r"(b[1]));
}
// split (f0, f1) -> bf16x2 hi-part h and residual-lo l  (lo half = f0)
__device__ __forceinline__ void bsplit(float f0, float f1, uint32_t& h, uint32_t& l) {
    h = cvt2bf(f1, f0);
    float r0 = __uint_as_float(h << 16);
    float r1 = __uint_as_float(h & 0xffff0000u);
    l = cvt2bf(f1 - r1, f0 - r0);
}

__device__ __forceinline__ void softmax_row(const float* row, int lane,
                                            float& m_out, float& sum_out)
{
    float m = -1e30f;
#pragma unroll
    for (int c = lane; c < HC; c += 32) m = fmaxf(m, row[c]);
#pragma unroll
    for (int o = 16; o > 0; o >>= 1) m = fmaxf(m, __shfl_xor_sync(0xffffffffu, m, o));
    float sum = 0.f;
#pragma unroll
    for (int c = lane; c < HC; c += 32) sum += __expf(row[c] - m);
#pragma unroll
    for (int o = 16; o > 0; o >>= 1) sum += __shfl_xor_sync(0xffffffffu, sum, o);
    m_out = m; sum_out = sum;
}

// ---------------------------------------------------------------------------
// Persistent HMMA kernel. 256 thr (8 warps), 2 CTAs/SM, queue of 384 items:
//   item < 256  : bottom parent (chunks of 16 rows; W[p] streamed from DRAM)
//   item >= 256 : top tile of 16 samples (W_top L2-resident)
// Per chunk: logits[16,256] = X[16,512] @ W[512,256] via m16n8k16 bf16 MMA,
// 3-term hi/lo split for fp32-grade accuracy. Warp w owns cols [32w, 32w+32).
// W register ring prefetch DEPTH 2 (R16 change; R15 was depth 1).
// ---------------------------------------------------------------------------
__global__ __launch_bounds__(NTHR, 2) void fused_kernel(
    const float* __restrict__ inputs, const int* __restrict__ labels,
    const int* __restrict__ parent,
    const float* __restrict__ topW, const float* __restrict__ topB,
    const float* __restrict__ botW, const float* __restrict__ botB,
    float* __restrict__ out)
{
    extern __shared__ char smc[];
    uint32_t sb = (uint32_t)__cvta_generic_to_shared(smc);
    float* lg   = (float*)(smc + OFF_LG);
    int* srows  = (int*)(smc + OFF_IDX);
    int* s_cnt  = (int*)(smc + OFF_CNT);
    int* s_pop  = (int*)(smc + OFF_POP);

    int tid = threadIdx.x;
    int wid = tid >> 5, lane = tid & 31;
    int lg4 = lane >> 2, l4 = lane & 3;
    int nb = wid * 32;

    // ldmatrix per-lane base address (row/col mapping for m16k16 A fragments)
    uint32_t lmoff = (uint32_t)((lane & 7) + ((lane >> 3) & 1) * 8) * XPITCH
                   + (uint32_t)((lane >> 4) * 8) * 2;
    uint32_t xh_lm = sb + OFF_XH + lmoff;
    uint32_t xl_lm = sb + OFF_XL + lmoff;

    for (;;) {
        __syncthreads();
        if (tid == 0) *s_pop = atomicAdd(&g_queue, 1);
        __syncthreads();
        int item = *s_pop;
        if (item >= NQ) break;

        bool isTop = (item >= HC);
        const float* Wp;
        const float* biasp;
        int n;
        if (isTop) {
            Wp = topW; biasp = topB;
            int b0 = (item - HC) * ROWS;
            if (tid < ROWS) srows[tid] = b0 + tid;
            n = ROWS;
            __syncthreads();
        } else {
            int p = item;
            Wp = botW + (size_t)p * NH * HC;
            biasp = botB + (size_t)p * HC;
            if (tid == 0) *s_cnt = 0;
            __syncthreads();
            for (int i = tid; i < BATCH; i += NTHR) {
                if (parent[i] == p) {
                    int q = atomicAdd(s_cnt, 1);
                    if (q < IDXCAP) srows[q] = i;
                }
            }
            __syncthreads();
            n = min(*s_cnt, IDXCAP);
            if (n == 0) continue;
        }

        for (int c0 = 0; c0 < n; c0 += ROWS) {
            int S = min(ROWS, n - c0);

            // ---- X -> smem bf16 hi/lo (rows >= S zero-filled) ----
            for (int idx = tid; idx < ROWS * 128; idx += NTHR) {
                int s = idx >> 7, kq = idx & 127;
                uint64_t hv = 0, lv = 0;
                if (s < S) {
                    int row = srows[c0 + s];
                    float4 v = __ldg((const float4*)(inputs + (size_t)row * NH) + kq);
                    uint32_t h01 = cvt2bf(v.y, v.x);
                    uint32_t h23 = cvt2bf(v.w, v.z);
                    float rx = __uint_as_float(h01 << 16);
                    float ry = __uint_as_float(h01 & 0xffff0000u);
                    float rz = __uint_as_float(h23 << 16);
                    float rw = __uint_as_float(h23 & 0xffff0000u);
                    uint32_t l01 = cvt2bf(v.y - ry, v.x - rx);
                    uint32_t l23 = cvt2bf(v.w - rw, v.z - rz);
                    hv = (uint64_t)h01 | ((uint64_t)h23 << 32);
                    lv = (uint64_t)l01 | ((uint64_t)l23 << 32);
                }
                uint32_t off = (uint32_t)s * XPITCH + (uint32_t)kq * 8;
                sts64(sb + OFF_XH + off, hv);
                sts64(sb + OFF_XL + off, lv);
            }
            __syncthreads();

            // ---- k-loop: 32 steps of k16, per-warp independent ----
            float acc[4][4];
#pragma unroll
            for (int nt = 0; nt < 4; nt++)
#pragma unroll
                for (int e = 0; e < 4; e++) acc[nt][e] = 0.f;

            // B element addresses: rows 2*l4 +{0,1,8,9}, col nb + lg4 + nt*8
            const float* wb = Wp + (size_t)(2 * l4) * HC + nb + lg4;

            // depth-2 W register ring: fr[0] = kstep 0, fr[1] = kstep 1
            float fr[2][4][4];
#pragma unroll
            for (int d = 0; d < 2; d++) {
                const float* wx = wb + (size_t)(d * 16) * HC;
#pragma unroll
                for (int nt = 0; nt < 4; nt++) {
                    const float* p = wx + nt * 8;
                    fr[d][nt][0] = __ldg(p);
                    fr[d][nt][1] = __ldg(p + HC);
                    fr[d][nt][2] = __ldg(p + 8 * HC);
                    fr[d][nt][3] = __ldg(p + 9 * HC);
                }
            }

#pragma unroll 2
            for (int ks = 0; ks < 32; ks++) {
                int buf = ks & 1;

                // A fragments first (smem latency hides under W DRAM loads)
                uint32_t Ah[4], Al[4];
                ldmx4(Ah, xh_lm + (uint32_t)ks * 32);
                ldmx4(Al, xl_lm + (uint32_t)ks * 32);

                // prefetch k-step ks+2 into temp (distance 2)
                float fn[4][4];
                int kn = (ks + 2 < 32) ? (ks + 2) : ks;
                const float* wnx = wb + (size_t)(kn * 16) * HC;
#pragma unroll
                for (int nt = 0; nt < 4; nt++) {
                    const float* p = wnx + nt * 8;
                    fn[nt][0] = __ldg(p);
                    fn[nt][1] = __ldg(p + HC);
                    fn[nt][2] = __ldg(p + 8 * HC);
                    fn[nt][3] = __ldg(p + 9 * HC);
                }

#pragma unroll
                for (int nt = 0; nt < 4; nt++) {
                    uint32_t bh[2], bl[2];
                    bsplit(fr[buf][nt][0], fr[buf][nt][1], bh[0], bl[0]);
                    bsplit(fr[buf][nt][2], fr[buf][nt][3], bh[1], bl[1]);
                    mma16816(acc[nt], Ah, bh);   // Wh * Xh
                    mma16816(acc[nt], Al, bh);   // Wh * Xl
                    mma16816(acc[nt], Ah, bl);   // Wl * Xh
                }
#pragma unroll
                for (int nt = 0; nt < 4; nt++)
#pragma unroll
                    for (int e = 0; e < 4; e++) fr[buf][nt][e] = fn[nt][e];
            }

            // ---- epilogue: acc + bias -> logits smem ----
#pragma unroll
            for (int nt = 0; nt < 4; nt++) {
                int c = nb + nt * 8 + 2 * l4;
                float2 bv = *(const float2*)(biasp + c);
                int g = lg4;
                lg[g * HC + c]           = acc[nt][0] + bv.x;
                lg[g * HC + c + 1]       = acc[nt][1] + bv.y;
                lg[(g + 8) * HC + c]     = acc[nt][2] + bv.x;
                lg[(g + 8) * HC + c + 1] = acc[nt][3] + bv.y;
            }
            __syncthreads();

            // ---- softmax + output (2 rows per warp) ----
            for (int r = wid; r < S; r += 8) {
                const float* row = lg + r * HC;
                float m, sum;
                softmax_row(row, lane, m, sum);
                if (lane == 0) {
                    int b = srows[c0 + r];
                    if (isTop) {
                        int pp = parent[b];
                        g_top_prob[b] = __expf(row[pp] - m) / sum;
                    } else {
                        int l = labels[b];
                        g_bot_prob[b] = __expf(row[l] - m) / sum;
                    }
                }
            }
            __syncthreads();   // smem reuse next chunk
        }
    }

    // ---- last-CTA finalize ----
    __syncthreads();
    __threadfence();
    if (tid == 0) *s_pop = atomicAdd(&g_done, 1);
    __syncthreads();
    if (*s_pop == GRID - 1) {
        __threadfence();
#pragma unroll
        for (int i = 0; i < BATCH / NTHR; i++) {
            int b = tid + i * NTHR;
            out[b] = g_top_prob[b] * g_bot_prob[b];
        }
        __threadfence();
        if (tid == 0) { g_done = 0; g_queue = 0; }
    }
}

// ---------------------------------------------------------------------------
extern "C" void kernel_launch(void* const* d_in, const int* in_sizes, int n_in,
                              void* d_out, int out_size) {
    const float* inputs = (const float*)d_in[0];
    const int*   labels = (const int*)d_in[1];
    const int*   parent = (const int*)d_in[2];
    const float* topW   = (const float*)d_in[3];
    const float* topB   = (const float*)d_in[4];
    const float* botW   = (const float*)d_in[5];
    const float* botB   = (const float*)d_in[6];
    float* out = (float*)d_out;

    cudaFuncSetAttribute(fused_kernel,
                         cudaFuncAttributeMaxDynamicSharedMemorySize, SMEM_BYTES);

    fused_kernel<<<GRID, NTHR, SMEM_BYTES>>>(inputs, labels, parent,
                                             topW, topB, botW, botB, out);
}

// round 17
// speedup vs baseline: 1.1466x; 1.1466x over previous
#include <cuda_runtime.h>
#include <cstdint>

#define BATCH 2048
#define NH    512
#define HC    256
#define ROWS  16            // rows per chunk (one m16 tile)
#define IDXCAP 128
#define GRID  296
#define NTOPI (BATCH / ROWS)       // 128 top items
#define NQ    (HC + NTOPI)         // 384 items
#define NTHR  256
#define XPITCH 1040         // 512 bf16 + 16B pad -> conflict-free ldmatrix

// smem byte offsets
#define OFF_XH  0                   // 16 * 1040
#define OFF_XL  16640
#define OFF_LG  33280               // 16*256*4
#define OFF_W   49664               // 8 warps * 3 stages * 2048B = 49152
#define OFF_IDX 98816
#define OFF_CNT (OFF_IDX + IDXCAP * 4)
#define OFF_POP (OFF_CNT + 4)
#define SMEM_BYTES (OFF_POP + 12)   // 99344 B -> 2 CTAs/SM (198.7KB <= 228KB)

__device__ float g_top_prob[BATCH];
__device__ float g_bot_prob[BATCH];
__device__ int   g_queue;
__device__ int   g_done;

// ---------------- PTX helpers (baseline ISA only) ----------
__device__ __forceinline__ uint32_t cvt2bf(float hi, float lo) {
    uint32_t r; asm("cvt.rn.bf16x2.f32 %0, %1, %2;" : "=r"(r) : "f"(hi), "f"(lo));
    return r;
}
__device__ __forceinline__ void sts64(uint32_t a, uint64_t v) {
    asm volatile("st.shared.b64 [%0], %1;" :: "r"(a), "l"(v));
}
__device__ __forceinline__ float lds32(uint32_t a) {
    float v; asm volatile("ld.shared.f32 %0, [%1];" : "=f"(v) : "r"(a)); return v;
}
__device__ __forceinline__ void ldmx4(uint32_t* r, uint32_t addr) {
    asm volatile("ldmatrix.sync.aligned.m8n8.x4.shared.b16 {%0,%1,%2,%3}, [%4];"
        : "=r"(r[0]), "=r"(r[1]), "=r"(r[2]), "=r"(r[3]) : "r"(addr));
}
__device__ __forceinline__ void mma16816(float* d, const uint32_t* a,
                                         const uint32_t* b) {
    asm volatile(
        "mma.sync.aligned.m16n8k16.row.col.f32.bf16.bf16.f32 "
        "{%0,%1,%2,%3}, {%4,%5,%6,%7}, {%8,%9}, {%0,%1,%2,%3};"
        : "+f"(d[0]), "+f"(d[1]), "+f"(d[2]), "+f"(d[3])
        : "r"(a[0]), "r"(a[1]), "r"(a[2]), "r"(a[3]), "r"(b[0]), "r"(b[1]));
}
__device__ __forceinline__ void cp16(uint32_t dst, const float* src) {
    asm volatile("cp.async.cg.shared.global [%0], [%1], 16;" :: "r"(dst), "l"(src) : "memory");
}
#define CP_COMMIT() asm volatile("cp.async.commit_group;" ::: "memory")
#define CP_WAIT2()  asm volatile("cp.async.wait_group 2;" ::: "memory")

// split (f0, f1) -> bf16x2 hi-part h and residual-lo l  (lo half = f0)
__device__ __forceinline__ void bsplit(float f0, float f1, uint32_t& h, uint32_t& l) {
    h = cvt2bf(f1, f0);
    float r0 = __uint_as_float(h << 16);
    float r1 = __uint_as_float(h & 0xffff0000u);
    l = cvt2bf(f1 - r1, f0 - r0);
}

// Issue one W stage: 16 k-rows x 32 cols fp32 (2KB), warp-private.
// Lane: row = lane>>1, col half = (lane&1)*16, 4 x 16B chunks.
__device__ __forceinline__ void issueW(uint32_t sW, const float* __restrict__ wsrc,
                                       int lane) {
    const float* src = wsrc + (size_t)(lane >> 1) * HC + (lane & 1) * 16;
    uint32_t dst = sW + (uint32_t)(lane >> 1) * 128 + (uint32_t)(lane & 1) * 64;
#pragma unroll
    for (int j = 0; j < 4; j++) cp16(dst + j * 16, src + j * 4);
    CP_COMMIT();
}

__device__ __forceinline__ void softmax_row(const float* row, int lane,
                                            float& m_out, float& sum_out)
{
    float m = -1e30f;
#pragma unroll
    for (int c = lane; c < HC; c += 32) m = fmaxf(m, row[c]);
#pragma unroll
    for (int o = 16; o > 0; o >>= 1) m = fmaxf(m, __shfl_xor_sync(0xffffffffu, m, o));
    float sum = 0.f;
#pragma unroll
    for (int c = lane; c < HC; c += 32) sum += __expf(row[c] - m);
#pragma unroll
    for (int o = 16; o > 0; o >>= 1) sum += __shfl_xor_sync(0xffffffffu, sum, o);
    m_out = m; sum_out = sum;
}

// ---------------------------------------------------------------------------
// Persistent HMMA kernel, cp.async warp-private W pipeline (3 stages x 2KB).
// 256 thr (8 warps), 2 CTAs/SM, queue of 384 items (256 bottom + 128 top).
// Per chunk: logits[16,256] = X[16,512] @ W[512,256], m16n8k16 bf16 MMA,
// 3-term hi/lo split. Warp w owns cols [32w, 32w+32). NO CTA barriers in
// the k-loop: each warp streams + consumes its own W slice.
// ---------------------------------------------------------------------------
__global__ __launch_bounds__(NTHR, 2) void fused_kernel(
    const float* __restrict__ inputs, const int* __restrict__ labels,
    const int* __restrict__ parent,
    const float* __restrict__ topW, const float* __restrict__ topB,
    const float* __restrict__ botW, const float* __restrict__ botB,
    float* __restrict__ out)
{
    extern __shared__ char smc[];
    uint32_t sb = (uint32_t)__cvta_generic_to_shared(smc);
    float* lg   = (float*)(smc + OFF_LG);
    int* srows  = (int*)(smc + OFF_IDX);
    int* s_cnt  = (int*)(smc + OFF_CNT);
    int* s_pop  = (int*)(smc + OFF_POP);

    int tid = threadIdx.x;
    int wid = tid >> 5, lane = tid & 31;
    int lg4 = lane >> 2, l4 = lane & 3;
    int nb = wid * 32;
    uint32_t wring = sb + OFF_W + (uint32_t)wid * 3 * 2048;

    // ldmatrix per-lane base address (m16k16 A fragment mapping)
    uint32_t lmoff = (uint32_t)((lane & 7) + ((lane >> 3) & 1) * 8) * XPITCH
                   + (uint32_t)((lane >> 4) * 8) * 2;
    uint32_t xh_lm = sb + OFF_XH + lmoff;
    uint32_t xl_lm = sb + OFF_XL + lmoff;

    // per-lane B-element offset within a 16x32 fp32 stage (pitch 128B):
    // rows {2*l4, 2*l4+1, 2*l4+8, 2*l4+9}, col lg4 (+8*nt later)
    uint32_t boff = (uint32_t)(2 * l4) * 128 + (uint32_t)lg4 * 4;

    for (;;) {
        __syncthreads();
        if (tid == 0) *s_pop = atomicAdd(&g_queue, 1);
        __syncthreads();
        int item = *s_pop;
        if (item >= NQ) break;

        bool isTop = (item >= HC);
        const float* Wp;
        const float* biasp;
        int n;
        if (isTop) {
            Wp = topW; biasp = topB;
            int b0 = (item - HC) * ROWS;
            if (tid < ROWS) srows[tid] = b0 + tid;
            n = ROWS;
            __syncthreads();
        } else {
            int p = item;
            Wp = botW + (size_t)p * NH * HC;
            biasp = botB + (size_t)p * HC;
            if (tid == 0) *s_cnt = 0;
            __syncthreads();
            for (int i = tid; i < BATCH; i += NTHR) {
                if (parent[i] == p) {
                    int q = atomicAdd(s_cnt, 1);
                    if (q < IDXCAP) srows[q] = i;
                }
            }
            __syncthreads();
            n = min(*s_cnt, IDXCAP);
            if (n == 0) continue;
        }

        const float* wwarp = Wp + nb;   // this warp's 32-column slice

        for (int c0 = 0; c0 < n; c0 += ROWS) {
            int S = min(ROWS, n - c0);

            // ---- W pipeline prologue (overlaps X conversion below) ----
#pragma unroll
            for (int st = 0; st < 3; st++)
                issueW(wring + (uint32_t)st * 2048, wwarp + (size_t)(st * 16) * HC, lane);

            // ---- X -> smem bf16 hi/lo (rows >= S zero-filled) ----
            for (int idx = tid; idx < ROWS * 128; idx += NTHR) {
                int s = idx >> 7, kq = idx & 127;
                uint64_t hv = 0, lv = 0;
                if (s < S) {
                    int row = srows[c0 + s];
                    float4 v = __ldg((const float4*)(inputs + (size_t)row * NH) + kq);
                    uint32_t h01 = cvt2bf(v.y, v.x);
                    uint32_t h23 = cvt2bf(v.w, v.z);
                    float rx = __uint_as_float(h01 << 16);
                    float ry = __uint_as_float(h01 & 0xffff0000u);
                    float rz = __uint_as_float(h23 << 16);
                    float rw = __uint_as_float(h23 & 0xffff0000u);
                    uint32_t l01 = cvt2bf(v.y - ry, v.x - rx);
                    uint32_t l23 = cvt2bf(v.w - rw, v.z - rz);
                    hv = (uint64_t)h01 | ((uint64_t)h23 << 32);
                    lv = (uint64_t)l01 | ((uint64_t)l23 << 32);
                }
                uint32_t off = (uint32_t)s * XPITCH + (uint32_t)kq * 8;
                sts64(sb + OFF_XH + off, hv);
                sts64(sb + OFF_XL + off, lv);
            }
            __syncthreads();

            // ---- k-loop: 32 steps of k16, warp-private W pipeline ----
            float acc[4][4];
#pragma unroll
            for (int nt = 0; nt < 4; nt++)
#pragma unroll
                for (int e = 0; e < 4; e++) acc[nt][e] = 0.f;

#pragma unroll 2
            for (int ks = 0; ks < 32; ks++) {
                CP_WAIT2();          // stage ks resident (<=2 groups outstanding)
                __syncwarp();

                uint32_t sW = wring + (uint32_t)(ks % 3) * 2048;

                uint32_t Ah[4], Al[4];
                ldmx4(Ah, xh_lm + (uint32_t)ks * 32);
                ldmx4(Al, xl_lm + (uint32_t)ks * 32);

#pragma unroll
                for (int nt = 0; nt < 4; nt++) {
                    uint32_t ba = sW + boff + (uint32_t)nt * 32;
                    float f0 = lds32(ba);
                    float f1 = lds32(ba + 128);
                    float f2 = lds32(ba + 1024);
                    float f3 = lds32(ba + 1152);
                    uint32_t bh[2], bl[2];
                    bsplit(f0, f1, bh[0], bl[0]);
                    bsplit(f2, f3, bh[1], bl[1]);
                    mma16816(acc[nt], Ah, bh);   // Wh * Xh
                    mma16816(acc[nt], Al, bh);   // Wh * Xl
                    mma16816(acc[nt], Ah, bl);   // Wl * Xh
                }

                __syncwarp();        // all lanes done reading stage ks%3
                int kn = ks + 3;
                if (kn < 32)
                    issueW(wring + (uint32_t)(kn % 3) * 2048,
                           wwarp + (size_t)(kn * 16) * HC, lane);
                else
                    CP_COMMIT();     // empty group keeps wait accounting uniform
            }

            // ---- epilogue: acc + bias -> logits smem ----
#pragma unroll
            for (int nt = 0; nt < 4; nt++) {
                int c = nb + nt * 8 + 2 * l4;
                float2 bv = *(const float2*)(biasp + c);
                int g = lg4;
                lg[g * HC + c]           = acc[nt][0] + bv.x;
                lg[g * HC + c + 1]       = acc[nt][1] + bv.y;
                lg[(g + 8) * HC + c]     = acc[nt][2] + bv.x;
                lg[(g + 8) * HC + c + 1] = acc[nt][3] + bv.y;
            }
            __syncthreads();

            // ---- softmax + output (2 rows per warp) ----
            for (int r = wid; r < S; r += 8) {
                const float* row = lg + r * HC;
                float m, sum;
                softmax_row(row, lane, m, sum);
                if (lane == 0) {
                    int b = srows[c0 + r];
                    if (isTop) {
                        int pp = parent[b];
                        g_top_prob[b] = __expf(row[pp] - m) / sum;
                    } else {
                        int l = labels[b];
                        g_bot_prob[b] = __expf(row[l] - m) / sum;
                    }
                }
            }
            __syncthreads();   // smem reuse next chunk
        }
    }

    // ---- last-CTA finalize ----
    __syncthreads();
    __threadfence();
    if (tid == 0) *s_pop = atomicAdd(&g_done, 1);
    __syncthreads();
    if (*s_pop == GRID - 1) {
        __threadfence();
#pragma unroll
        for (int i = 0; i < BATCH / NTHR; i++) {
            int b = tid + i * NTHR;
            out[b] = g_top_prob[b] * g_bot_prob[b];
        }
        __threadfence();
        if (tid == 0) { g_done = 0; g_queue = 0; }
    }
}

// ---------------------------------------------------------------------------
extern "C" void kernel_launch(void* const* d_in, const int* in_sizes, int n_in,
                              void* d_out, int out_size) {
    const float* inputs = (const float*)d_in[0];
    const int*   labels = (const int*)d_in[1];
    const int*   parent = (const int*)d_in[2];
    const float* topW   = (const float*)d_in[3];
    const float* topB   = (const float*)d_in[4];
    const float* botW   = (const float*)d_in[5];
    const float* botB   = (const float*)d_in[6];
    float* out = (float*)d_out;

    cudaFuncSetAttribute(fused_kernel,
                         cudaFuncAttributeMaxDynamicSharedMemorySize, SMEM_BYTES);

    fused_kernel<<<GRID, NTHR, SMEM_BYTES>>>(inputs, labels, parent,
                                             topW, topB, botW, botB, out);
}